// round 8
// baseline (speedup 1.0000x reference)
#include <cuda_runtime.h>
#include <math_constants.h>
#include <cstdint>

#define BATCH   2
#define S_LEN   2048
#define D_MODEL 1024
#define NH      16
#define HDIM    64

// ---------------- scratch ----------------------------------------------------
__device__ float g_q[BATCH * NH * S_LEN * HDIM];     // [B,H,S,64]
__device__ float g_k[BATCH * NH * S_LEN * HDIM];
__device__ float g_v[BATCH * NH * S_LEN * HDIM];
__device__ float g_att[BATCH * S_LEN * D_MODEL];     // [B,S,H*64]

// ---------------- 3xTF32 mma.sync GEMM ----------------------------------------
// C[4096,1024] = A[4096,1024] @ W[1024,1024] + bias
// CTA 128x128, BK=32, 8 warps (2x4), warp tile 64x32, mma.m16n8k8.tf32.
// Splits (hi/lo tf32) hoisted into smem at staging; inner loop = LDS + MMA only.
// Gmem loads for chunk c+1 prefetched into registers during chunk c's MMAs.
#define BM 128
#define BN 128
#define BK 32
#define NCHUNK (D_MODEL / BK)

__device__ __forceinline__ void mma_tf32(float c[4], const uint32_t a[4],
                                         const uint32_t b[2]) {
    asm volatile(
        "mma.sync.aligned.m16n8k8.row.col.f32.tf32.tf32.f32 "
        "{%0,%1,%2,%3}, {%4,%5,%6,%7}, {%8,%9}, {%0,%1,%2,%3};\n"
        : "+f"(c[0]), "+f"(c[1]), "+f"(c[2]), "+f"(c[3])
        : "r"(a[0]), "r"(a[1]), "r"(a[2]), "r"(a[3]), "r"(b[0]), "r"(b[1]));
}

__device__ __forceinline__ uint32_t f2tf32(float x) {
    uint32_t r;
    asm("cvt.rna.tf32.f32 %0, %1;" : "=r"(r) : "f"(x));
    return r;
}
__device__ __forceinline__ void tf32_split(float x, float& hi, float& lo) {
    uint32_t h = f2tf32(x);
    hi = __uint_as_float(h);
    lo = __uint_as_float(f2tf32(x - hi));
}

// MODE 0: row-major out. MODE 1: scatter to [B,H,S,64]
template <int MODE>
__device__ __forceinline__ void gemm_mma_body(const float* __restrict__ A,
                                              const float* __restrict__ W,
                                              const float* __restrict__ bias,
                                              float* __restrict__ C)
{
    __shared__ float Ah[BK][BM + 4];   // tf32-hi of A^T tile
    __shared__ float Al[BK][BM + 4];   // tf32-lo
    __shared__ float Bh[BK][BN + 4];
    __shared__ float Bl[BK][BN + 4];

    const int tid  = threadIdx.x;
    const int wid  = tid >> 5;
    const int lane = tid & 31;
    const int g    = lane >> 2;     // 0..7
    const int t    = lane & 3;      // 0..3
    const int wm   = wid >> 2;      // 0..1
    const int wn   = wid & 3;       // 0..3
    const int bm   = blockIdx.y * BM;
    const int bn   = blockIdx.x * BN;

    float c[4][4][4];
#pragma unroll
    for (int i = 0; i < 4; i++)
#pragma unroll
        for (int j = 0; j < 4; j++)
#pragma unroll
            for (int f = 0; f < 4; f++) c[i][j][f] = 0.f;

    const int a_m = tid >> 3;            // 0..31 (+32/pass)
    const int a_k = (tid & 7) << 2;      // 0,4,...,28
    const int b_k = tid >> 5;            // 0..7  (+8/pass)
    const int b_n = (tid & 31) << 2;     // 0..124

    float4 ra[4], rb[4];
    // prefetch chunk 0
#pragma unroll
    for (int p = 0; p < 4; p++) {
        ra[p] = *(const float4*)(A + (size_t)(bm + a_m + p * 32) * D_MODEL + a_k);
        rb[p] = *(const float4*)(W + (size_t)(b_k + p * 8) * D_MODEL + bn + b_n);
    }

    for (int ch = 0; ch < NCHUNK; ch++) {
        // split + store current regs -> smem
#pragma unroll
        for (int p = 0; p < 4; p++) {
            const int m = a_m + p * 32;
            tf32_split(ra[p].x, Ah[a_k + 0][m], Al[a_k + 0][m]);
            tf32_split(ra[p].y, Ah[a_k + 1][m], Al[a_k + 1][m]);
            tf32_split(ra[p].z, Ah[a_k + 2][m], Al[a_k + 2][m]);
            tf32_split(ra[p].w, Ah[a_k + 3][m], Al[a_k + 3][m]);
            const int k = b_k + p * 8;
            tf32_split(rb[p].x, Bh[k][b_n + 0], Bl[k][b_n + 0]);
            tf32_split(rb[p].y, Bh[k][b_n + 1], Bl[k][b_n + 1]);
            tf32_split(rb[p].z, Bh[k][b_n + 2], Bl[k][b_n + 2]);
            tf32_split(rb[p].w, Bh[k][b_n + 3], Bl[k][b_n + 3]);
        }
        __syncthreads();

        // prefetch next chunk (latency hidden under MMAs below)
        if (ch + 1 < NCHUNK) {
            const int k0 = (ch + 1) * BK;
#pragma unroll
            for (int p = 0; p < 4; p++) {
                ra[p] = *(const float4*)(A + (size_t)(bm + a_m + p * 32) * D_MODEL + k0 + a_k);
                rb[p] = *(const float4*)(W + (size_t)(k0 + b_k + p * 8) * D_MODEL + bn + b_n);
            }
        }

#pragma unroll
        for (int s = 0; s < 4; s++) {
            const int kk = s * 8;
            uint32_t ah[4][4], al[4][4], bh[4][2], bl[4][2];
#pragma unroll
            for (int i = 0; i < 4; i++) {
                const int mb = wm * 64 + i * 16;
                ah[i][0] = __float_as_uint(Ah[kk + t    ][mb + g    ]);
                ah[i][1] = __float_as_uint(Ah[kk + t    ][mb + g + 8]);
                ah[i][2] = __float_as_uint(Ah[kk + t + 4][mb + g    ]);
                ah[i][3] = __float_as_uint(Ah[kk + t + 4][mb + g + 8]);
                al[i][0] = __float_as_uint(Al[kk + t    ][mb + g    ]);
                al[i][1] = __float_as_uint(Al[kk + t    ][mb + g + 8]);
                al[i][2] = __float_as_uint(Al[kk + t + 4][mb + g    ]);
                al[i][3] = __float_as_uint(Al[kk + t + 4][mb + g + 8]);
            }
#pragma unroll
            for (int j = 0; j < 4; j++) {
                const int nb = wn * 32 + j * 8;
                bh[j][0] = __float_as_uint(Bh[kk + t    ][nb + g]);
                bh[j][1] = __float_as_uint(Bh[kk + t + 4][nb + g]);
                bl[j][0] = __float_as_uint(Bl[kk + t    ][nb + g]);
                bl[j][1] = __float_as_uint(Bl[kk + t + 4][nb + g]);
            }
#pragma unroll
            for (int i = 0; i < 4; i++)
#pragma unroll
                for (int j = 0; j < 4; j++) {
                    mma_tf32(c[i][j], al[i], bh[j]);
                    mma_tf32(c[i][j], ah[i], bl[j]);
                    mma_tf32(c[i][j], ah[i], bh[j]);
                }
        }
        __syncthreads();
    }

#pragma unroll
    for (int i = 0; i < 4; i++) {
#pragma unroll
        for (int j = 0; j < 4; j++) {
            const int col = bn + wn * 32 + j * 8 + 2 * t;
            const float bx = bias[col], by = bias[col + 1];
#pragma unroll
            for (int h2 = 0; h2 < 2; h2++) {
                const int row = bm + wm * 64 + i * 16 + g + h2 * 8;
                float2 o;
                o.x = c[i][j][h2 * 2 + 0] + bx;
                o.y = c[i][j][h2 * 2 + 1] + by;
                if (MODE == 0) {
                    *(float2*)(C + (size_t)row * D_MODEL + col) = o;
                } else {
                    const int b_ = row >> 11, s_ = row & (S_LEN - 1);
                    const int h_ = col >> 6,  d_ = col & 63;
                    *(float2*)(C + (((size_t)b_ * NH + h_) * S_LEN + s_) * HDIM + d_) = o;
                }
            }
        }
    }
}

__global__ __launch_bounds__(256, 1) void gemm_qkv_mma(
    const float* __restrict__ x,
    const float* __restrict__ Wq, const float* __restrict__ bq,
    const float* __restrict__ Wk, const float* __restrict__ bk,
    const float* __restrict__ Wv, const float* __restrict__ bv)
{
    const float* W; const float* bias; float* out;
    if (blockIdx.z == 0)      { W = Wq; bias = bq; out = g_q; }
    else if (blockIdx.z == 1) { W = Wk; bias = bk; out = g_k; }
    else                      { W = Wv; bias = bv; out = g_v; }
    gemm_mma_body<1>(x, W, bias, out);
}

__global__ __launch_bounds__(256, 1) void gemm_out_mma(
    const float* __restrict__ Wo, const float* __restrict__ bo,
    float* __restrict__ out)
{
    gemm_mma_body<0>(g_att, Wo, bo, out);
}

// ---------------- flash attention ---------------------------------------------
#define FBR 128
#define FBC 32
#define FLASH_SMEM_BYTES ((64 * 128 + 64 * FBC + FBC * 64 + FBC) * 4)

__global__ __launch_bounds__(128) void flash_kernel(const unsigned char* __restrict__ mask)
{
    extern __shared__ float fsm[];
    float* qst = fsm;
    float* Kst = fsm + 64 * 128;
    float* Vs  = fsm + 64 * 128 + 64 * FBC;
    int*   maskS = (int*)(fsm + 64 * 128 + 64 * FBC + FBC * 64);

    const int tid = threadIdx.x;
    const int qt  = (gridDim.x - 1) - blockIdx.x;
    const int h   = blockIdx.y;
    const int b   = blockIdx.z;
    const size_t bh = (size_t)b * NH + h;
    const float* qb = g_q + bh * S_LEN * HDIM;
    const float* kb = g_k + bh * S_LEN * HDIM;
    const float* vb = g_v + bh * S_LEN * HDIM;

#pragma unroll
    for (int p = 0; p < 16; p++) {
        const int idx = p * 128 + tid;
        const int row = idx >> 4;
        const int d4  = (idx & 15) << 2;
        float4 qv = *(const float4*)(qb + (size_t)(qt * FBR + row) * HDIM + d4);
        qst[(d4 + 0) * 128 + row] = qv.x;
        qst[(d4 + 1) * 128 + row] = qv.y;
        qst[(d4 + 2) * 128 + row] = qv.z;
        qst[(d4 + 3) * 128 + row] = qv.w;
    }

    float acc[HDIM];
#pragma unroll
    for (int d = 0; d < HDIM; d++) acc[d] = 0.f;
    float mrow = -CUDART_INF_F;
    float lrow = 0.f;

    const int row_g = qt * FBR + tid;
    const int nkt   = (qt + 1) * (FBR / FBC);
    const int diag0 = qt * (FBR / FBC);

    for (int kt = 0; kt < nkt; kt++) {
        __syncthreads();
#pragma unroll
        for (int p = 0; p < 4; p++) {
            const int idx = p * 128 + tid;
            const int j   = idx >> 4;
            const int d4  = (idx & 15) << 2;
            const size_t goff = (size_t)(kt * FBC + j) * HDIM + d4;
            float4 kv = *(const float4*)(kb + goff);
            Kst[(d4 + 0) * FBC + j] = kv.x;
            Kst[(d4 + 1) * FBC + j] = kv.y;
            Kst[(d4 + 2) * FBC + j] = kv.z;
            Kst[(d4 + 3) * FBC + j] = kv.w;
            *(float4*)(Vs + j * HDIM + d4) = *(const float4*)(vb + goff);
        }
        if (tid < FBC) maskS[tid] = mask[(size_t)b * S_LEN + kt * FBC + tid];
        __syncthreads();

        float s[FBC];
#pragma unroll
        for (int j = 0; j < FBC; j++) s[j] = 0.f;
#pragma unroll 4
        for (int d = 0; d < HDIM; d++) {
            const float qd = qst[d * 128 + tid];
#pragma unroll
            for (int j4 = 0; j4 < 8; j4++) {
                float4 kk = *(float4*)(Kst + d * FBC + j4 * 4);
                s[j4 * 4 + 0] = fmaf(qd, kk.x, s[j4 * 4 + 0]);
                s[j4 * 4 + 1] = fmaf(qd, kk.y, s[j4 * 4 + 1]);
                s[j4 * 4 + 2] = fmaf(qd, kk.z, s[j4 * 4 + 2]);
                s[j4 * 4 + 3] = fmaf(qd, kk.w, s[j4 * 4 + 3]);
            }
        }

        float tmax = -CUDART_INF_F;
        const bool need_causal = (kt >= diag0);
#pragma unroll
        for (int j = 0; j < FBC; j++) {
            float sv = s[j] * 0.125f;
            if ((need_causal && (kt * FBC + j > row_g)) || maskS[j])
                sv = -CUDART_INF_F;
            s[j] = sv;
            tmax = fmaxf(tmax, sv);
        }

        // rescale only when the running max actually rises
        if (tmax > mrow) {
            const float scale = (mrow > -CUDART_INF_F) ? __expf(mrow - tmax) : 0.f;
            mrow = tmax;
            lrow *= scale;
#pragma unroll
            for (int d = 0; d < HDIM; d++) acc[d] *= scale;
        }
        if (tmax > -CUDART_INF_F) {
            float psum = 0.f;
#pragma unroll
            for (int j = 0; j < FBC; j++) {
                const float p = __expf(s[j] - mrow);
                s[j] = p;
                psum += p;
            }
            lrow += psum;
#pragma unroll
            for (int j = 0; j < FBC; j++) {
                const float pj = s[j];
#pragma unroll
                for (int d4 = 0; d4 < 16; d4++) {
                    float4 vv = *(float4*)(Vs + j * HDIM + d4 * 4);
                    acc[d4 * 4 + 0] = fmaf(pj, vv.x, acc[d4 * 4 + 0]);
                    acc[d4 * 4 + 1] = fmaf(pj, vv.y, acc[d4 * 4 + 1]);
                    acc[d4 * 4 + 2] = fmaf(pj, vv.z, acc[d4 * 4 + 2]);
                    acc[d4 * 4 + 3] = fmaf(pj, vv.w, acc[d4 * 4 + 3]);
                }
            }
        }
    }

    const float inv = 1.f / lrow;
    float* op = g_att + ((size_t)b * S_LEN + row_g) * D_MODEL + h * HDIM;
#pragma unroll
    for (int d4 = 0; d4 < 16; d4++) {
        float4 w;
        w.x = acc[d4 * 4 + 0] * inv;
        w.y = acc[d4 * 4 + 1] * inv;
        w.z = acc[d4 * 4 + 2] * inv;
        w.w = acc[d4 * 4 + 3] * inv;
        *(float4*)(op + d4 * 4) = w;
    }
}

// ---------------- launch ------------------------------------------------------
extern "C" void kernel_launch(void* const* d_in, const int* in_sizes, int n_in,
                              void* d_out, int out_size)
{
    const float* x  = (const float*)d_in[0];
    const unsigned char* mask = (const unsigned char*)d_in[1];
    const float* Wq = (const float*)d_in[2];
    const float* bq = (const float*)d_in[3];
    const float* Wk = (const float*)d_in[4];
    const float* bk = (const float*)d_in[5];
    const float* Wv = (const float*)d_in[6];
    const float* bv = (const float*)d_in[7];
    const float* Wo = (const float*)d_in[8];
    const float* bo = (const float*)d_in[9];
    float* out = (float*)d_out;

    cudaFuncSetAttribute(flash_kernel,
                         cudaFuncAttributeMaxDynamicSharedMemorySize,
                         FLASH_SMEM_BYTES);

    // 1) QKV projections (3xTF32 mma.sync, hoisted splits, prefetched)
    dim3 gq(D_MODEL / BN, (BATCH * S_LEN) / BM, 3);
    gemm_qkv_mma<<<gq, 256>>>(x, Wq, bq, Wk, bk, Wv, bv);

    // 2) causal flash attention
    dim3 gf(S_LEN / FBR, NH, BATCH);
    flash_kernel<<<gf, 128, FLASH_SMEM_BYTES>>>(mask);

    // 3) output projection
    dim3 go(D_MODEL / BN, (BATCH * S_LEN) / BM, 1);
    gemm_out_mma<<<go, 256>>>(Wo, bo, out);
}

// round 9
// speedup vs baseline: 1.3389x; 1.3389x over previous
#include <cuda_runtime.h>
#include <cuda_bf16.h>
#include <math_constants.h>
#include <cstdint>

#define BATCH   2
#define S_LEN   2048
#define D_MODEL 1024
#define NH      16
#define HDIM    64

// ---------------- scratch ----------------------------------------------------
__device__ float g_q[BATCH * NH * S_LEN * HDIM];     // [B,H,S,64]
__device__ float g_k[BATCH * NH * S_LEN * HDIM];
__device__ float g_v[BATCH * NH * S_LEN * HDIM];
__device__ float g_att[BATCH * S_LEN * D_MODEL];     // [B,S,H*64]

// ---------------- bf16x3 mma.sync GEMM ----------------------------------------
// C[4096,1024] = A[4096,1024] @ W[1024,1024] + bias
// CTA 128x128, BK=32, 8 warps (2x4), warp tile 64x32, mma.m16n8k16.bf16.
// fp32 emulated as ah*bh + ah*bl + al*bh (al/bl = bf16 residuals).
#define BM 128
#define BN 128
#define BK 32
#define NCHUNK (D_MODEL / BK)
#define TSTR 40   // smem tile row stride in halfs (bank-conflict-free frags)

__device__ __forceinline__ void mma_bf16(float c[4], const uint32_t a[4],
                                         const uint32_t b[2]) {
    asm volatile(
        "mma.sync.aligned.m16n8k16.row.col.f32.bf16.bf16.f32 "
        "{%0,%1,%2,%3}, {%4,%5,%6,%7}, {%8,%9}, {%0,%1,%2,%3};\n"
        : "+f"(c[0]), "+f"(c[1]), "+f"(c[2]), "+f"(c[3])
        : "r"(a[0]), "r"(a[1]), "r"(a[2]), "r"(a[3]), "r"(b[0]), "r"(b[1]));
}

// split two fp32 into packed bf16 hi pair + lo pair
__device__ __forceinline__ void split2(float x0, float x1,
                                       uint32_t& hp, uint32_t& lp) {
    __nv_bfloat16 h0 = __float2bfloat16(x0);
    __nv_bfloat16 h1 = __float2bfloat16(x1);
    __nv_bfloat16 l0 = __float2bfloat16(x0 - __bfloat162float(h0));
    __nv_bfloat16 l1 = __float2bfloat16(x1 - __bfloat162float(h1));
    hp = (uint32_t)__bfloat16_as_ushort(h0) |
         ((uint32_t)__bfloat16_as_ushort(h1) << 16);
    lp = (uint32_t)__bfloat16_as_ushort(l0) |
         ((uint32_t)__bfloat16_as_ushort(l1) << 16);
}

// MODE 0: row-major out. MODE 1: scatter to [B,H,S,64]
template <int MODE>
__device__ __forceinline__ void gemm_mma_body(const float* __restrict__ A,
                                              const float* __restrict__ W,
                                              const float* __restrict__ bias,
                                              float* __restrict__ C)
{
    __shared__ unsigned short AhS[BM * TSTR], AlS[BM * TSTR];
    __shared__ unsigned short BhS[BN * TSTR], BlS[BN * TSTR];

    const int tid  = threadIdx.x;
    const int wid  = tid >> 5;
    const int lane = tid & 31;
    const int g    = lane >> 2;     // 0..7
    const int t    = lane & 3;      // 0..3
    const int wm   = wid >> 2;      // 0..1
    const int wn   = wid & 3;       // 0..3
    const int bm   = blockIdx.y * BM;
    const int bn   = blockIdx.x * BN;

    float c[4][4][4];
#pragma unroll
    for (int i = 0; i < 4; i++)
#pragma unroll
        for (int j = 0; j < 4; j++)
#pragma unroll
            for (int f = 0; f < 4; f++) c[i][j][f] = 0.f;

    // A staging: float4 along k. m = am+32p, k cols ak..ak+3
    const int am = tid >> 3;            // 0..31
    const int ak = (tid & 7) << 2;      // 0,4,...,28
    // B staging: 4 scalars along k (coalesced along n). n = bnn, k = bk4+8p+i
    const int bnn = tid & 127;
    const int bk4 = (tid >> 7) << 2;    // 0 or 4

    float4 ra[4];
    float  rw[16];
#pragma unroll
    for (int p = 0; p < 4; p++) {
        ra[p] = *(const float4*)(A + (size_t)(bm + am + p * 32) * D_MODEL + ak);
#pragma unroll
        for (int i = 0; i < 4; i++)
            rw[p * 4 + i] = W[(size_t)(bk4 + 8 * p + i) * D_MODEL + bn + bnn];
    }

    for (int ch = 0; ch < NCHUNK; ch++) {
        // split + store current registers
#pragma unroll
        for (int p = 0; p < 4; p++) {
            const int m = am + p * 32;
            uint2 vh, vl;
            split2(ra[p].x, ra[p].y, vh.x, vl.x);
            split2(ra[p].z, ra[p].w, vh.y, vl.y);
            *(uint2*)(AhS + m * TSTR + ak) = vh;
            *(uint2*)(AlS + m * TSTR + ak) = vl;
            const int k = bk4 + 8 * p;
            split2(rw[p * 4 + 0], rw[p * 4 + 1], vh.x, vl.x);
            split2(rw[p * 4 + 2], rw[p * 4 + 3], vh.y, vl.y);
            *(uint2*)(BhS + bnn * TSTR + k) = vh;
            *(uint2*)(BlS + bnn * TSTR + k) = vl;
        }
        __syncthreads();

        // prefetch next chunk
        if (ch + 1 < NCHUNK) {
            const int k0 = (ch + 1) * BK;
#pragma unroll
            for (int p = 0; p < 4; p++) {
                ra[p] = *(const float4*)(A + (size_t)(bm + am + p * 32) * D_MODEL + k0 + ak);
#pragma unroll
                for (int i = 0; i < 4; i++)
                    rw[p * 4 + i] = W[(size_t)(k0 + bk4 + 8 * p + i) * D_MODEL + bn + bnn];
            }
        }

#pragma unroll
        for (int ks = 0; ks < 2; ks++) {
            const int kk = ks * 16;
            uint32_t ah[4][4], al[4][4], bh[4][2], bl[4][2];
#pragma unroll
            for (int i = 0; i < 4; i++) {
                const int mb = wm * 64 + i * 16;
                const unsigned short* ph = AhS + (mb + g) * TSTR + kk + 2 * t;
                const unsigned short* pl = AlS + (mb + g) * TSTR + kk + 2 * t;
                ah[i][0] = *(const uint32_t*)(ph);
                ah[i][1] = *(const uint32_t*)(ph + 8 * TSTR);
                ah[i][2] = *(const uint32_t*)(ph + 8);
                ah[i][3] = *(const uint32_t*)(ph + 8 * TSTR + 8);
                al[i][0] = *(const uint32_t*)(pl);
                al[i][1] = *(const uint32_t*)(pl + 8 * TSTR);
                al[i][2] = *(const uint32_t*)(pl + 8);
                al[i][3] = *(const uint32_t*)(pl + 8 * TSTR + 8);
            }
#pragma unroll
            for (int j = 0; j < 4; j++) {
                const int nb = wn * 32 + j * 8;
                const unsigned short* ph = BhS + (nb + g) * TSTR + kk + 2 * t;
                const unsigned short* pl = BlS + (nb + g) * TSTR + kk + 2 * t;
                bh[j][0] = *(const uint32_t*)(ph);
                bh[j][1] = *(const uint32_t*)(ph + 8);
                bl[j][0] = *(const uint32_t*)(pl);
                bl[j][1] = *(const uint32_t*)(pl + 8);
            }
#pragma unroll
            for (int i = 0; i < 4; i++)
#pragma unroll
                for (int j = 0; j < 4; j++) {
                    mma_bf16(c[i][j], al[i], bh[j]);
                    mma_bf16(c[i][j], ah[i], bl[j]);
                    mma_bf16(c[i][j], ah[i], bh[j]);
                }
        }
        __syncthreads();
    }

#pragma unroll
    for (int i = 0; i < 4; i++) {
#pragma unroll
        for (int j = 0; j < 4; j++) {
            const int col = bn + wn * 32 + j * 8 + 2 * t;
            const float bx = bias[col], by = bias[col + 1];
#pragma unroll
            for (int h2 = 0; h2 < 2; h2++) {
                const int row = bm + wm * 64 + i * 16 + g + h2 * 8;
                float2 o;
                o.x = c[i][j][h2 * 2 + 0] + bx;
                o.y = c[i][j][h2 * 2 + 1] + by;
                if (MODE == 0) {
                    *(float2*)(C + (size_t)row * D_MODEL + col) = o;
                } else {
                    const int b_ = row >> 11, s_ = row & (S_LEN - 1);
                    const int h_ = col >> 6,  d_ = col & 63;
                    *(float2*)(C + (((size_t)b_ * NH + h_) * S_LEN + s_) * HDIM + d_) = o;
                }
            }
        }
    }
}

__global__ __launch_bounds__(256, 1) void gemm_qkv_mma(
    const float* __restrict__ x,
    const float* __restrict__ Wq, const float* __restrict__ bq,
    const float* __restrict__ Wk, const float* __restrict__ bk,
    const float* __restrict__ Wv, const float* __restrict__ bv)
{
    const float* W; const float* bias; float* out;
    if (blockIdx.z == 0)      { W = Wq; bias = bq; out = g_q; }
    else if (blockIdx.z == 1) { W = Wk; bias = bk; out = g_k; }
    else                      { W = Wv; bias = bv; out = g_v; }
    gemm_mma_body<1>(x, W, bias, out);
}

__global__ __launch_bounds__(256, 1) void gemm_out_mma(
    const float* __restrict__ Wo, const float* __restrict__ bo,
    float* __restrict__ out)
{
    gemm_mma_body<0>(g_att, Wo, bo, out);
}

// ---------------- flash attention: 2 threads per query row --------------------
// 256 threads = 128 rows x 2. Pair = adjacent lanes (shfl-mergeable).
// Thread handles 16 of 32 scores (jh half) and 32 of 64 output dims
// (interleaved: d = m*8 + jh*4 + q).
#define FBR 128
#define FBC 32
#define FLASH_SMEM_BYTES ((64 * 128 + 64 * FBC + FBC * 64 + FBC) * 4)

__global__ __launch_bounds__(256) void flash_kernel(const unsigned char* __restrict__ mask)
{
    extern __shared__ float fsm[];
    float* qst = fsm;                        // [64][128]  qst[d][row]
    float* Kst = fsm + 64 * 128;             // [64][32]   Kst[d][j]
    float* Vs  = fsm + 64 * 128 + 64 * FBC;  // [32][64]   Vs[j][d]
    int*   maskS = (int*)(fsm + 64 * 128 + 64 * FBC + FBC * 64);

    const int tid = threadIdx.x;
    const int row = tid >> 1;       // 0..127
    const int jh  = tid & 1;        // score/dim half
    const int qt  = (gridDim.x - 1) - blockIdx.x;
    const int h   = blockIdx.y;
    const int b   = blockIdx.z;
    const size_t bh = (size_t)b * NH + h;
    const float* qb = g_q + bh * S_LEN * HDIM;
    const float* kb = g_k + bh * S_LEN * HDIM;
    const float* vb = g_v + bh * S_LEN * HDIM;

    // stage Q tile transposed (256 threads, 8 passes)
#pragma unroll
    for (int p = 0; p < 8; p++) {
        const int idx = p * 256 + tid;
        const int rq  = idx >> 4;
        const int d4  = (idx & 15) << 2;
        float4 qv = *(const float4*)(qb + (size_t)(qt * FBR + rq) * HDIM + d4);
        qst[(d4 + 0) * 128 + rq] = qv.x;
        qst[(d4 + 1) * 128 + rq] = qv.y;
        qst[(d4 + 2) * 128 + rq] = qv.z;
        qst[(d4 + 3) * 128 + rq] = qv.w;
    }

    float4 acc4[8];
#pragma unroll
    for (int m = 0; m < 8; m++) acc4[m] = make_float4(0.f, 0.f, 0.f, 0.f);
    float mrow = -CUDART_INF_F;
    float lrow = 0.f;

    const int row_g = qt * FBR + row;
    const int nkt   = (qt + 1) * (FBR / FBC);
    const int diag0 = qt * (FBR / FBC);
    const int jbase = jh * 16;

    for (int kt = 0; kt < nkt; kt++) {
        __syncthreads();
        // stage K^T and V (2 passes)
#pragma unroll
        for (int p = 0; p < 2; p++) {
            const int idx = p * 256 + tid;
            const int j   = idx >> 4;
            const int d4  = (idx & 15) << 2;
            const size_t goff = (size_t)(kt * FBC + j) * HDIM + d4;
            float4 kv = *(const float4*)(kb + goff);
            Kst[(d4 + 0) * FBC + j] = kv.x;
            Kst[(d4 + 1) * FBC + j] = kv.y;
            Kst[(d4 + 2) * FBC + j] = kv.z;
            Kst[(d4 + 3) * FBC + j] = kv.w;
            *(float4*)(Vs + j * HDIM + d4) = *(const float4*)(vb + goff);
        }
        if (tid < FBC) maskS[tid] = mask[(size_t)b * S_LEN + kt * FBC + tid];
        __syncthreads();

        // scores for this thread's 16 j's
        float s[16];
#pragma unroll
        for (int jj = 0; jj < 16; jj++) s[jj] = 0.f;
#pragma unroll 4
        for (int d = 0; d < HDIM; d++) {
            const float qd = qst[d * 128 + row];
#pragma unroll
            for (int j4 = 0; j4 < 4; j4++) {
                float4 kk = *(float4*)(Kst + d * FBC + jbase + j4 * 4);
                s[j4 * 4 + 0] = fmaf(qd, kk.x, s[j4 * 4 + 0]);
                s[j4 * 4 + 1] = fmaf(qd, kk.y, s[j4 * 4 + 1]);
                s[j4 * 4 + 2] = fmaf(qd, kk.z, s[j4 * 4 + 2]);
                s[j4 * 4 + 3] = fmaf(qd, kk.w, s[j4 * 4 + 3]);
            }
        }

        float tmax = -CUDART_INF_F;
        const bool need_causal = (kt >= diag0);
#pragma unroll
        for (int jj = 0; jj < 16; jj++) {
            float sv = s[jj] * 0.125f;
            if ((need_causal && (kt * FBC + jbase + jj > row_g)) || maskS[jbase + jj])
                sv = -CUDART_INF_F;
            s[jj] = sv;
            tmax = fmaxf(tmax, sv);
        }
        tmax = fmaxf(tmax, __shfl_xor_sync(0xffffffffu, tmax, 1));

        if (tmax > mrow) {   // pair-consistent; no shfl inside
            const float scale = (mrow > -CUDART_INF_F) ? __expf(mrow - tmax) : 0.f;
            mrow = tmax;
            lrow *= scale;
#pragma unroll
            for (int m = 0; m < 8; m++) {
                acc4[m].x *= scale; acc4[m].y *= scale;
                acc4[m].z *= scale; acc4[m].w *= scale;
            }
        }
        const float msafe = (mrow == -CUDART_INF_F) ? 0.f : mrow;

        float psum = 0.f;
#pragma unroll
        for (int jj = 0; jj < 16; jj++) {
            const float p = __expf(s[jj] - msafe);
            s[jj] = p;
            psum += p;
        }
        psum += __shfl_xor_sync(0xffffffffu, psum, 1);
        lrow += psum;

        // exchange partner's p's (convergent)
        float po[16];
#pragma unroll
        for (int jj = 0; jj < 16; jj++)
            po[jj] = __shfl_xor_sync(0xffffffffu, s[jj], 1);

        // PV over this thread's 32 dims: d = m*8 + jh*4 + q
        const int dof = jh * 4;
#pragma unroll
        for (int jj = 0; jj < 16; jj++) {       // j = jj (half 0)
            const float pj = jh ? po[jj] : s[jj];
#pragma unroll
            for (int m = 0; m < 8; m++) {
                float4 vv = *(float4*)(Vs + jj * HDIM + m * 8 + dof);
                acc4[m].x = fmaf(pj, vv.x, acc4[m].x);
                acc4[m].y = fmaf(pj, vv.y, acc4[m].y);
                acc4[m].z = fmaf(pj, vv.z, acc4[m].z);
                acc4[m].w = fmaf(pj, vv.w, acc4[m].w);
            }
        }
#pragma unroll
        for (int jj = 0; jj < 16; jj++) {       // j = 16 + jj (half 1)
            const float pj = jh ? s[jj] : po[jj];
#pragma unroll
            for (int m = 0; m < 8; m++) {
                float4 vv = *(float4*)(Vs + (16 + jj) * HDIM + m * 8 + dof);
                acc4[m].x = fmaf(pj, vv.x, acc4[m].x);
                acc4[m].y = fmaf(pj, vv.y, acc4[m].y);
                acc4[m].z = fmaf(pj, vv.z, acc4[m].z);
                acc4[m].w = fmaf(pj, vv.w, acc4[m].w);
            }
        }
    }

    const float inv = 1.f / lrow;
    float* op = g_att + ((size_t)b * S_LEN + row_g) * D_MODEL + h * HDIM + jh * 4;
#pragma unroll
    for (int m = 0; m < 8; m++) {
        float4 w;
        w.x = acc4[m].x * inv;
        w.y = acc4[m].y * inv;
        w.z = acc4[m].z * inv;
        w.w = acc4[m].w * inv;
        *(float4*)(op + m * 8) = w;
    }
}

// ---------------- launch ------------------------------------------------------
extern "C" void kernel_launch(void* const* d_in, const int* in_sizes, int n_in,
                              void* d_out, int out_size)
{
    const float* x  = (const float*)d_in[0];
    const unsigned char* mask = (const unsigned char*)d_in[1];
    const float* Wq = (const float*)d_in[2];
    const float* bq = (const float*)d_in[3];
    const float* Wk = (const float*)d_in[4];
    const float* bk = (const float*)d_in[5];
    const float* Wv = (const float*)d_in[6];
    const float* bv = (const float*)d_in[7];
    const float* Wo = (const float*)d_in[8];
    const float* bo = (const float*)d_in[9];
    float* out = (float*)d_out;

    cudaFuncSetAttribute(flash_kernel,
                         cudaFuncAttributeMaxDynamicSharedMemorySize,
                         FLASH_SMEM_BYTES);

    // 1) QKV projections (bf16x3 mma.sync)
    dim3 gq(D_MODEL / BN, (BATCH * S_LEN) / BM, 3);
    gemm_qkv_mma<<<gq, 256>>>(x, Wq, bq, Wk, bk, Wv, bv);

    // 2) causal flash attention (split-j, 256 threads)
    dim3 gf(S_LEN / FBR, NH, BATCH);
    flash_kernel<<<gf, 256, FLASH_SMEM_BYTES>>>(mask);

    // 3) output projection
    dim3 go(D_MODEL / BN, (BATCH * S_LEN) / BM, 1);
    gemm_out_mma<<<go, 256>>>(Wo, bo, out);
}